// round 1
// baseline (speedup 1.0000x reference)
#include <cuda_runtime.h>
#include <cuda_bf16.h>
#include <mma.h>

using namespace nvcuda;

#define B_  128
#define T_  512
#define C_  384
#define NH_ 6
#define HD_ 64

// ---------------- scratch (device globals: allocation-free) ----------------
__device__ float g_qkv[(size_t)B_ * T_ * 3 * C_];   // [B,T,3C]   302 MB
__device__ float g_q[(size_t)B_ * NH_ * T_ * HD_];  // [B,NH,T,HD] 100 MB
__device__ float g_k[(size_t)B_ * NH_ * T_ * HD_];
__device__ float g_v[(size_t)B_ * NH_ * T_ * HD_];
__device__ float g_o[(size_t)B_ * T_ * C_];         // [B,T,C]

// ---------------------------------------------------------------------------
// GEMM (NT): C[M,N] = A[M,K] @ B[N,K]^T, fp32 in/out, tf32 tensor cores.
// BM=128, BN=64, BK=32, 256 threads (8 warps), warp tile 32x32.
// ---------------------------------------------------------------------------
__global__ void __launch_bounds__(256) gemm_nt_tf32(
    const float* __restrict__ A, const float* __restrict__ Bw,
    float* __restrict__ Cc, int M, int N, int K)
{
    __shared__ float smA[128][36];
    __shared__ float smB[64][36];

    const int tid = threadIdx.x;
    const int w   = tid >> 5;
    const int bm  = blockIdx.y * 128;
    const int bn  = blockIdx.x * 64;
    const int m_off = (w >> 1) * 32;
    const int n_off = (w & 1) * 32;

    wmma::fragment<wmma::accumulator, 16, 16, 8, float> acc[2][2];
    #pragma unroll
    for (int i = 0; i < 2; i++)
        #pragma unroll
        for (int j = 0; j < 2; j++)
            wmma::fill_fragment(acc[i][j], 0.0f);

    for (int k0 = 0; k0 < K; k0 += 32) {
        // Load A tile 128x32
        #pragma unroll
        for (int p = 0; p < 4; p++) {
            int r  = (tid >> 3) + p * 32;
            int c4 = (tid & 7) * 4;
            *(float4*)&smA[r][c4] =
                *(const float4*)&A[(size_t)(bm + r) * K + k0 + c4];
        }
        // Load B tile 64x32
        #pragma unroll
        for (int p = 0; p < 2; p++) {
            int r  = (tid >> 3) + p * 32;
            int c4 = (tid & 7) * 4;
            *(float4*)&smB[r][c4] =
                *(const float4*)&Bw[(size_t)(bn + r) * K + k0 + c4];
        }
        __syncthreads();

        #pragma unroll
        for (int kk = 0; kk < 32; kk += 8) {
            wmma::fragment<wmma::matrix_a, 16, 16, 8, wmma::precision::tf32, wmma::row_major> af[2];
            wmma::fragment<wmma::matrix_b, 16, 16, 8, wmma::precision::tf32, wmma::col_major> bf[2];
            #pragma unroll
            for (int i = 0; i < 2; i++) {
                wmma::load_matrix_sync(af[i], &smA[m_off + 16 * i][kk], 36);
                #pragma unroll
                for (int e = 0; e < af[i].num_elements; e++)
                    af[i].x[e] = wmma::__float_to_tf32(af[i].x[e]);
            }
            #pragma unroll
            for (int j = 0; j < 2; j++) {
                wmma::load_matrix_sync(bf[j], &smB[n_off + 16 * j][kk], 36);
                #pragma unroll
                for (int e = 0; e < bf[j].num_elements; e++)
                    bf[j].x[e] = wmma::__float_to_tf32(bf[j].x[e]);
            }
            #pragma unroll
            for (int i = 0; i < 2; i++)
                #pragma unroll
                for (int j = 0; j < 2; j++)
                    wmma::mma_sync(acc[i][j], af[i], bf[j], acc[i][j]);
        }
        __syncthreads();
    }

    #pragma unroll
    for (int i = 0; i < 2; i++)
        #pragma unroll
        for (int j = 0; j < 2; j++)
            wmma::store_matrix_sync(
                &Cc[(size_t)(bm + m_off + 16 * i) * N + bn + n_off + 16 * j],
                acc[i][j], N, wmma::mem_row_major);
}

// ---------------------------------------------------------------------------
// RoPE + split + transpose: g_qkv[B,T,3,NH,HD] -> g_q/g_k/g_v [B,NH,T,HD]
// rot = [r1*c - r2*s, r2*c + r1*s] on first 16 dims of q,k.
// ---------------------------------------------------------------------------
__global__ void rope_split(const float* __restrict__ qkv,
                           const float* __restrict__ cosb,
                           const float* __restrict__ sinb,
                           float* __restrict__ q, float* __restrict__ k,
                           float* __restrict__ v)
{
    int idx = blockIdx.x * blockDim.x + threadIdx.x; // over B*NH*T*HD
    int d  = idx & 63;
    int t  = (idx >> 6) & 511;
    int hb = idx >> 15;              // b*NH + h
    int h  = hb % NH_;
    int b  = hb / NH_;

    size_t ibase = ((size_t)b * T_ + t) * (3 * C_) + h * HD_ + d;
    float qv = qkv[ibase];
    float kv = qkv[ibase + C_];
    float vv = qkv[ibase + 2 * C_];

    if (d < 16) {
        if (d < 8) {
            float c = cosb[t * 8 + d], s = sinb[t * 8 + d];
            float q2 = qkv[ibase + 8], k2 = qkv[ibase + C_ + 8];
            qv = qv * c - q2 * s;
            kv = kv * c - k2 * s;
        } else {
            int j = d - 8;
            float c = cosb[t * 8 + j], s = sinb[t * 8 + j];
            float q1 = qkv[ibase - 8], k1 = qkv[ibase + C_ - 8];
            qv = qv * c + q1 * s;
            kv = kv * c + k1 * s;
        }
    }
    q[idx] = qv;
    k[idx] = kv;
    v[idx] = vv;
}

// ---------------------------------------------------------------------------
// Attention: one block per (b, h, q-tile of 64). Full score strip [64 x 512]
// in smem (no online softmax needed at T=512), causal via valid-length loops.
// S = Q K^T (tf32 wmma), softmax fp32, O = P V (tf32 wmma) -> g_o [B,T,C].
// ---------------------------------------------------------------------------
#define SLD 520
#define QLD 72
#define ATTN_SMEM ((2 * 64 * QLD + 64 * SLD) * 4)

__global__ void __launch_bounds__(256) attn_kernel(
    const float* __restrict__ q, const float* __restrict__ k,
    const float* __restrict__ v, float* __restrict__ o)
{
    extern __shared__ float sh[];
    float* sQ  = sh;                  // 64 x 72
    float* sKV = sh + 64 * QLD;       // 64 x 72 (K then V, reused)
    float* sS  = sh + 2 * 64 * QLD;   // 64 x 520

    const int qt = blockIdx.x, h = blockIdx.y, b = blockIdx.z;
    const int tid = threadIdx.x, w = tid >> 5, lane = tid & 31;
    const int nkt = qt + 1;

    const float* qbase = q + (((size_t)b * NH_ + h) * T_ + qt * 64) * HD_;
    const float* kbase = k + (((size_t)b * NH_ + h) * T_) * HD_;
    const float* vbase = v + (((size_t)b * NH_ + h) * T_) * HD_;

    // Load Q tile 64x64
    #pragma unroll
    for (int p = 0; p < 4; p++) {
        int r  = (tid >> 4) + p * 16;
        int c4 = (tid & 15) * 4;
        *(float4*)&sQ[r * QLD + c4] = *(const float4*)&qbase[r * 64 + c4];
    }

    const int m_off = (w >> 1) * 16;   // 4 warp rows x 16
    const int n_off = (w & 1) * 32;    // 2 warp cols x 32

    // ---- S phase: S[:, kt*64 : kt*64+64] = scale * Q K_kt^T ----
    for (int kt = 0; kt < nkt; kt++) {
        __syncthreads();
        #pragma unroll
        for (int p = 0; p < 4; p++) {
            int r  = (tid >> 4) + p * 16;
            int c4 = (tid & 15) * 4;
            *(float4*)&sKV[r * QLD + c4] =
                *(const float4*)&kbase[(kt * 64 + r) * 64 + c4];
        }
        __syncthreads();

        wmma::fragment<wmma::accumulator, 16, 16, 8, float> sc[2];
        #pragma unroll
        for (int j = 0; j < 2; j++) wmma::fill_fragment(sc[j], 0.0f);

        #pragma unroll
        for (int kk = 0; kk < 64; kk += 8) {
            wmma::fragment<wmma::matrix_a, 16, 16, 8, wmma::precision::tf32, wmma::row_major> af;
            wmma::load_matrix_sync(af, &sQ[m_off * QLD + kk], QLD);
            #pragma unroll
            for (int e = 0; e < af.num_elements; e++)
                af.x[e] = wmma::__float_to_tf32(af.x[e]);
            #pragma unroll
            for (int j = 0; j < 2; j++) {
                wmma::fragment<wmma::matrix_b, 16, 16, 8, wmma::precision::tf32, wmma::col_major> bf;
                wmma::load_matrix_sync(bf, &sKV[(n_off + 16 * j) * QLD + kk], QLD);
                #pragma unroll
                for (int e = 0; e < bf.num_elements; e++)
                    bf.x[e] = wmma::__float_to_tf32(bf.x[e]);
                wmma::mma_sync(sc[j], af, bf, sc[j]);
            }
        }
        #pragma unroll
        for (int j = 0; j < 2; j++) {
            #pragma unroll
            for (int e = 0; e < sc[j].num_elements; e++) sc[j].x[e] *= 0.125f;
            wmma::store_matrix_sync(&sS[m_off * SLD + kt * 64 + n_off + 16 * j],
                                    sc[j], SLD, wmma::mem_row_major);
        }
    }
    __syncthreads();

    // ---- softmax (causal): warp w handles rows w*8 .. w*8+7 ----
    const int L = nkt * 64;
    for (int rr = 0; rr < 8; rr++) {
        int r    = w * 8 + rr;
        int vlen = qt * 64 + r + 1;   // causal valid length
        float mx = -1e30f;
        for (int j = lane; j < vlen; j += 32) mx = fmaxf(mx, sS[r * SLD + j]);
        #pragma unroll
        for (int off = 16; off > 0; off >>= 1)
            mx = fmaxf(mx, __shfl_xor_sync(0xffffffffu, mx, off));
        float sum = 0.f;
        for (int j = lane; j < vlen; j += 32) {
            float e = __expf(sS[r * SLD + j] - mx);
            sS[r * SLD + j] = e;
            sum += e;
        }
        #pragma unroll
        for (int off = 16; off > 0; off >>= 1)
            sum += __shfl_xor_sync(0xffffffffu, sum, off);
        float inv = 1.0f / sum;
        for (int j = lane; j < vlen; j += 32) sS[r * SLD + j] *= inv;
        for (int j = vlen + lane; j < L; j += 32) sS[r * SLD + j] = 0.f;
    }

    // ---- O phase: O = P V (accumulate over k-tiles) ----
    wmma::fragment<wmma::accumulator, 16, 16, 8, float> oacc[2];
    #pragma unroll
    for (int j = 0; j < 2; j++) wmma::fill_fragment(oacc[j], 0.0f);

    for (int kt = 0; kt < nkt; kt++) {
        __syncthreads();
        #pragma unroll
        for (int p = 0; p < 4; p++) {
            int r  = (tid >> 4) + p * 16;
            int c4 = (tid & 15) * 4;
            *(float4*)&sKV[r * QLD + c4] =
                *(const float4*)&vbase[(kt * 64 + r) * 64 + c4];
        }
        __syncthreads();

        #pragma unroll
        for (int kk = 0; kk < 64; kk += 8) {
            wmma::fragment<wmma::matrix_a, 16, 16, 8, wmma::precision::tf32, wmma::row_major> af;
            wmma::load_matrix_sync(af, &sS[m_off * SLD + kt * 64 + kk], SLD);
            #pragma unroll
            for (int e = 0; e < af.num_elements; e++)
                af.x[e] = wmma::__float_to_tf32(af.x[e]);
            #pragma unroll
            for (int j = 0; j < 2; j++) {
                wmma::fragment<wmma::matrix_b, 16, 16, 8, wmma::precision::tf32, wmma::row_major> bf;
                wmma::load_matrix_sync(bf, &sKV[kk * QLD + n_off + 16 * j], QLD);
                #pragma unroll
                for (int e = 0; e < bf.num_elements; e++)
                    bf.x[e] = wmma::__float_to_tf32(bf.x[e]);
                wmma::mma_sync(oacc[j], af, bf, oacc[j]);
            }
        }
    }

    // Store O tile into g_o [B,T,C]: rows t = qt*64 + m, cols c = h*64 + n
    #pragma unroll
    for (int j = 0; j < 2; j++)
        wmma::store_matrix_sync(
            &o[((size_t)b * T_ + qt * 64 + m_off) * C_ + h * HD_ + n_off + 16 * j],
            oacc[j], C_, wmma::mem_row_major);
}

// ---------------------------------------------------------------------------
extern "C" void kernel_launch(void* const* d_in, const int* in_sizes, int n_in,
                              void* d_out, int out_size)
{
    const float* x    = (const float*)d_in[0]; // [B,T,C]
    const float* Wqkv = (const float*)d_in[1]; // [3C,C]
    const float* Wout = (const float*)d_in[2]; // [C,C]
    const float* cosb = (const float*)d_in[3]; // [1,1,512,8]
    const float* sinb = (const float*)d_in[4];
    float* out = (float*)d_out;                // [B,T,C]

    float *qkv, *q, *k, *v, *o;
    cudaGetSymbolAddress((void**)&qkv, g_qkv);
    cudaGetSymbolAddress((void**)&q,   g_q);
    cudaGetSymbolAddress((void**)&k,   g_k);
    cudaGetSymbolAddress((void**)&v,   g_v);
    cudaGetSymbolAddress((void**)&o,   g_o);

    const int M = B_ * T_; // 65536

    // K1: qkv = x @ Wqkv^T   [65536 x 1152]
    {
        dim3 grid((3 * C_) / 64, M / 128);
        gemm_nt_tf32<<<grid, 256>>>(x, Wqkv, qkv, M, 3 * C_, C_);
    }
    // K2: RoPE + split + transpose
    {
        int total = B_ * NH_ * T_ * HD_; // 25165824
        rope_split<<<total / 256, 256>>>(qkv, cosb, sinb, q, k, v);
    }
    // K3: causal attention
    {
        cudaFuncSetAttribute(attn_kernel,
                             cudaFuncAttributeMaxDynamicSharedMemorySize,
                             ATTN_SMEM);
        dim3 grid(T_ / 64, NH_, B_);
        attn_kernel<<<grid, 256, ATTN_SMEM>>>(q, k, v, o);
    }
    // K4: out = o @ Wout^T   [65536 x 384]
    {
        dim3 grid(C_ / 64, M / 128);
        gemm_nt_tf32<<<grid, 256>>>(o, Wout, out, M, C_, C_);
    }
}